// round 6
// baseline (speedup 1.0000x reference)
#include <cuda_runtime.h>
#include <cuda_bf16.h>
#include <math.h>

// Problem constants
#define B_   8
#define C_   8
#define K_   10
#define D_   512
#define H_   96
#define W_   96
#define HW_  (H_*W_)          // 9216
#define NPIX (B_*HW_)         // 73728
#define SEGS 16               // k2 segments (6 rows each)

// ---------------- scratch (__device__ globals; no allocations) ----------------
// prototypes packed: g_P2[d2][c*20 + k*2 + parity], row stride 160 floats
__device__ __align__(16) float g_P2[256 * 160];                 // 160 KB
__device__ __align__(16) float g_S[(size_t)NPIX * 12];          // 3.5 MB normalized sims
__device__ float g_MomSeg[64 * SEGS * 66];                      // per-(bc,seg) moments
__device__ int   g_cnt[64];                                     // class pixel counts per (b,c)

__constant__ int cPK[45] = {0,0,0,0,0,0,0,0,0, 1,1,1,1,1,1,1,1, 2,2,2,2,2,2,2,
                            3,3,3,3,3,3, 4,4,4,4,4, 5,5,5,5, 6,6,6, 7,7, 8};
__constant__ int cPL[45] = {1,2,3,4,5,6,7,8,9, 2,3,4,5,6,7,8,9, 3,4,5,6,7,8,9,
                            4,5,6,7,8,9, 5,6,7,8,9, 6,7,8,9, 7,8,9, 8,9, 9};

// ---- f32x2 packed helpers ----
__device__ __forceinline__ unsigned long long pk2(float a, float b) {
    unsigned long long r;
    asm("mov.b64 %0, {%1, %2};" : "=l"(r) : "f"(a), "f"(b));
    return r;
}
__device__ __forceinline__ void ffma2(unsigned long long& d, unsigned long long a, unsigned long long b) {
    asm("fma.rn.f32x2 %0, %1, %2, %0;" : "+l"(d) : "l"(a), "l"(b));
}
__device__ __forceinline__ void add2(unsigned long long& d, unsigned long long a) {
    asm("add.rn.f32x2 %0, %0, %1;" : "+l"(d) : "l"(a));
}
__device__ __forceinline__ float upsum(unsigned long long v) {
    float lo, hi;
    asm("mov.b64 {%0, %1}, %2;" : "=f"(lo), "=f"(hi) : "l"(v));
    return lo + hi;
}
__device__ __forceinline__ void unpk(unsigned long long v, float& lo, float& hi) {
    asm("mov.b64 {%0, %1}, %2;" : "=f"(lo), "=f"(hi) : "l"(v));
}

// ---------------- k0: normalize prototypes into packed layout + zero g_cnt ----------------
__global__ void k0_norm_proto(const float* __restrict__ P) {
    int blk = blockIdx.x;
    int tid = threadIdx.x;          // 128
    if (blk == 80) {
        if (tid < 64) g_cnt[tid] = 0;
        return;
    }
    const float* row = P + blk * D_;
    float ss = 0.f;
    for (int i = tid; i < D_; i += 128) { float v = row[i]; ss = fmaf(v, v, ss); }
    #pragma unroll
    for (int o = 16; o; o >>= 1) ss += __shfl_xor_sync(0xffffffffu, ss, o);
    __shared__ float red[4];
    if ((tid & 31) == 0) red[tid >> 5] = ss;
    __syncthreads();
    float tot = red[0] + red[1] + red[2] + red[3];
    float inv = 1.0f / fmaxf(sqrtf(tot), 1e-12f);
    int c = blk / K_, k = blk % K_;
    for (int d = tid; d < D_; d += 128)
        g_P2[(d >> 1) * 160 + c * 20 + k * 2 + (d & 1)] = row[d] * inv;
}

// ---------------- k1: class-bucketed sims, single pass, writes g_S ----------------
// grid = 288 (NPIX/256); block = 256 threads. Pixels class-sorted so warps are
// (nearly) class-uniform -> prototype SMEM reads broadcast.
__global__ __launch_bounds__(256) void k1_sim(const float* __restrict__ F,
                                              const int* __restrict__ mask) {
    __shared__ float sF[32 * 256];                 // 32 KB F chunk [d_local][pixel-slot]
    __shared__ __align__(16) float sp[16 * 160];   // 10 KB proto chunk
    __shared__ int order[256];
    __shared__ int ocls[256];
    __shared__ int cnt[9], off[9];

    int tid = threadIdx.x;
    int blk = blockIdx.x;
    int pix = blk * 256 + tid;          // flat global pixel (256 | 9216 => no image straddle)
    int b   = pix / HW_;
    int pin = pix - b * HW_;

    if (tid < 9) cnt[tid] = 0;
    int m = mask[pix];
    __syncthreads();
    int slot = atomicAdd(&cnt[m], 1);
    __syncthreads();
    if (tid == 0) {
        int o = 0;
        #pragma unroll
        for (int cc = 0; cc < 9; cc++) { off[cc] = o; o += cnt[cc]; }
    }
    __syncthreads();
    int myslot = off[m] + slot;
    order[myslot] = tid;
    ocls[myslot] = m;
    __syncthreads();

    int q  = order[tid];                // pixel slot this thread processes
    int mq = ocls[tid];
    int cq = (mq > 0) ? (mq - 1) : 0;
    int pbase_cq = cq * 20;

    const float* fbt = F + (size_t)b * D_ * HW_ + pin;   // for coalesced staging (own tid)

    unsigned long long n2 = 0ull;
    unsigned long long s2[10];
    #pragma unroll
    for (int k = 0; k < 10; k++) s2[k] = 0ull;

    // prologue: prefetch chunk 0 into registers
    float r[32];
    #pragma unroll
    for (int i = 0; i < 32; i++) r[i] = fbt[(size_t)i * HW_];

    for (int ch = 0; ch < 16; ch++) {
        // store staged chunk (conflict-free: bank = tid%32)
        #pragma unroll
        for (int i = 0; i < 32; i++) sF[i * 256 + tid] = r[i];
        // stage proto chunk (16 d2-rows x 160 floats)
        {
            const float4* src = (const float4*)(g_P2 + (size_t)ch * 16 * 160);
            float4* dst = (float4*)sp;
            #pragma unroll
            for (int i = 0; i < 3; i++) {
                int idx = tid + i * 256;
                if (idx < 640) dst[idx] = src[idx];
            }
        }
        __syncthreads();
        // prefetch next chunk while computing
        if (ch < 15) {
            const float* fn = fbt + (size_t)(ch + 1) * 32 * HW_;
            #pragma unroll
            for (int i = 0; i < 32; i++) r[i] = fn[(size_t)i * HW_];
        }
        // compute 16 d-pairs
        #pragma unroll
        for (int d2 = 0; d2 < 16; d2++) {
            unsigned long long f2 = pk2(sF[(2 * d2) * 256 + q], sF[(2 * d2 + 1) * 256 + q]);
            const ulonglong2* qp = (const ulonglong2*)(sp + d2 * 160 + pbase_cq);
            ulonglong2 q0 = qp[0], q1 = qp[1], q2 = qp[2], q3 = qp[3], q4 = qp[4];
            ffma2(n2, f2, f2);
            ffma2(s2[0], f2, q0.x); ffma2(s2[1], f2, q0.y);
            ffma2(s2[2], f2, q1.x); ffma2(s2[3], f2, q1.y);
            ffma2(s2[4], f2, q2.x); ffma2(s2[5], f2, q2.y);
            ffma2(s2[6], f2, q3.x); ffma2(s2[7], f2, q3.y);
            ffma2(s2[8], f2, q4.x); ffma2(s2[9], f2, q4.y);
        }
        __syncthreads();
    }

    if (mq > 0) {
        float nrm = upsum(n2);
        float inv = 1.0f / fmaxf(sqrtf(nrm), 1e-12f);
        float4* o = (float4*)(g_S + (size_t)(blk * 256 + q) * 12);
        o[0] = make_float4(upsum(s2[0]) * inv, upsum(s2[1]) * inv,
                           upsum(s2[2]) * inv, upsum(s2[3]) * inv);
        o[1] = make_float4(upsum(s2[4]) * inv, upsum(s2[5]) * inv,
                           upsum(s2[6]) * inv, upsum(s2[7]) * inv);
        o[2] = make_float4(upsum(s2[8]) * inv, upsum(s2[9]) * inv, 0.f, 0.f);
    }
    if (tid < 8) atomicAdd(&g_cnt[b * 8 + tid], cnt[tid + 1]);
}

// ---------------- k2: preload stripe, fused horiz+vert pool + moments ----------------
// grid = 64*SEGS: blk = bc*SEGS + seg (6 output rows); block = 96 threads (one per w).
// SMEM: S transposed as f32x2 pairs: sSP[(j*5+cp)*192 + px*2 + par], 12 rows.
__global__ __launch_bounds__(96) void k2_fused(const int* __restrict__ mask) {
    __shared__ float sSP[12 * 5 * 192];          // 46.1 KB
    __shared__ unsigned char sMk[12 * 96];       // 1.2 KB
    __shared__ float red[3][66];

    int blk = blockIdx.x;
    int bc  = blk / SEGS;
    int seg = blk - bc * SEGS;
    int b = bc >> 3, c = bc & 7;
    int w = threadIdx.x;
    int h0 = seg * 6;

    // preload 12 rows (h0-3 .. h0+8) of S (transposed) and mask
    for (int idx = w; idx < 12 * 288; idx += 96) {
        int j = idx / 288, t = idx - j * 288;
        int hh = h0 - 3 + j;
        int px = t / 3, part = t - px * 3;
        float4 v = make_float4(0.f, 0.f, 0.f, 0.f);
        if ((unsigned)hh < 96u)
            v = ((const float4*)(g_S + (size_t)(b * HW_ + hh * W_ + px) * 12))[part];
        float* base = sSP + (size_t)j * 5 * 192;
        if (part < 2) {
            int cp = part * 2;
            base[cp * 192 + px * 2]           = v.x;
            base[cp * 192 + px * 2 + 1]       = v.y;
            base[(cp + 1) * 192 + px * 2]     = v.z;
            base[(cp + 1) * 192 + px * 2 + 1] = v.w;
        } else {
            base[4 * 192 + px * 2]     = v.x;
            base[4 * 192 + px * 2 + 1] = v.y;
        }
    }
    #pragma unroll
    for (int j = 0; j < 12; j++) {
        int hh = h0 - 3 + j;
        sMk[j * 96 + w] = ((unsigned)hh < 96u)
            ? (unsigned char)mask[b * HW_ + hh * W_ + w] : (unsigned char)0;
    }
    __syncthreads();

    float ringv[7][11];
    float vs[11];
    #pragma unroll
    for (int i = 0; i < 11; i++) vs[i] = 0.f;
    float V = 0.f;
    float Sr[10]; float M[55];
    #pragma unroll
    for (int k = 0; k < 10; k++) Sr[k] = 0.f;
    #pragma unroll
    for (int i = 0; i < 55; i++) M[i] = 0.f;

    unsigned char cm = (unsigned char)(c + 1);

    #pragma unroll
    for (int j = 0; j < 12; j++) {
        // horizontal masked 7-tap (packed f32x2 accumulation)
        unsigned long long pp[5] = {0ull, 0ull, 0ull, 0ull, 0ull};
        float pcnt = 0.f;
        const float* base = sSP + (size_t)j * 5 * 192;
        #pragma unroll
        for (int dw = -3; dw <= 3; dw++) {
            int ww = w + dw;
            if ((unsigned)ww < 96u && sMk[j * 96 + ww] == cm) {
                #pragma unroll
                for (int cp = 0; cp < 5; cp++) {
                    unsigned long long sv = *(const unsigned long long*)(base + cp * 192 + ww * 2);
                    add2(pp[cp], sv);
                }
                pcnt += 1.f;
            }
        }
        // unpack, slide window
        float pr[11];
        #pragma unroll
        for (int cp = 0; cp < 5; cp++) unpk(pp[cp], pr[cp * 2], pr[cp * 2 + 1]);
        pr[10] = pcnt;
        #pragma unroll
        for (int i = 0; i < 11; i++) { vs[i] += pr[i]; ringv[j % 7][i] = pr[i]; }

        if (j >= 6) {
            float den = vs[10] * (1.0f / 49.0f);
            if (den > 0.05f) {
                float inv = 1.0f / (den + 1e-8f);
                float r[10];
                #pragma unroll
                for (int k = 0; k < 10; k++) r[k] = (vs[k] * (1.0f / 49.0f)) * inv;
                V += 1.f;
                #pragma unroll
                for (int k = 0; k < 10; k++) Sr[k] += r[k];
                int idx = 0;
                #pragma unroll
                for (int k = 0; k < 10; k++)
                    #pragma unroll
                    for (int l = k; l < 10; l++) { M[idx] = fmaf(r[k], r[l], M[idx]); idx++; }
            }
            #pragma unroll
            for (int i = 0; i < 11; i++) vs[i] -= ringv[(j - 6) % 7][i];
        }
    }

    // warp butterfly reduce (3 warps, same (bc,seg))
    #pragma unroll
    for (int o = 16; o; o >>= 1) V += __shfl_xor_sync(0xffffffffu, V, o);
    #pragma unroll
    for (int k = 0; k < 10; k++) {
        float v = Sr[k];
        #pragma unroll
        for (int o = 16; o; o >>= 1) v += __shfl_xor_sync(0xffffffffu, v, o);
        Sr[k] = v;
    }
    #pragma unroll
    for (int i = 0; i < 55; i++) {
        float v = M[i];
        #pragma unroll
        for (int o = 16; o; o >>= 1) v += __shfl_xor_sync(0xffffffffu, v, o);
        M[i] = v;
    }
    int lane = w & 31, wid = w >> 5;
    if (lane == 0) {
        red[wid][0] = V;
        #pragma unroll
        for (int k = 0; k < 10; k++) red[wid][1 + k] = Sr[k];
        #pragma unroll
        for (int i = 0; i < 55; i++) red[wid][11 + i] = M[i];
    }
    __syncthreads();
    if (w < 66)
        g_MomSeg[(size_t)blk * 66 + w] = red[0][w] + red[1][w] + red[2][w];
}

// ---------------- k3: finalize scalar (1 block, 32 warps; warp per 2 bc) ----------------
__global__ __launch_bounds__(1024) void k3(float* __restrict__ out) {
    __shared__ float sM[64][66];
    __shared__ float sla[64], saf[64];
    int tid = threadIdx.x;
    int wi = tid >> 5, lane = tid & 31;

    #pragma unroll
    for (int t = wi * 2; t < wi * 2 + 2; t++) {
        for (int i = lane; i < 66; i += 32) {
            float s = 0.f;
            #pragma unroll
            for (int seg = 0; seg < SEGS; seg++) s += g_MomSeg[(size_t)(t * SEGS + seg) * 66 + i];
            sM[t][i] = s;
        }
        __syncwarp();
        const float* mm = sM[t];
        float V = mm[0];
        float Vf = fmaxf(V, 1.0f);
        float invVf = 1.0f / Vf;

        float Srk = 0.f, nk = 0.f;
        if (lane < 10) {
            Srk = mm[1 + lane];
            int di = 10 * lane - lane * (lane - 1) / 2;
            float cv = mm[11 + di] - Srk * Srk * invVf;
            nk = sqrtf(fmaxf(cv, 0.f));
        }
        float Sr[10], n[10];
        #pragma unroll
        for (int k = 0; k < 10; k++) {
            Sr[k] = __shfl_sync(0xffffffffu, Srk, k);
            n[k]  = __shfl_sync(0xffffffffu, nk, k);
        }
        float acci = 0.f;
        #pragma unroll
        for (int rep = 0; rep < 2; rep++) {
            int p = lane + rep * 32;
            if (p < 45) {
                int k = cPK[p], l = cPL[p];
                int idx = 10 * k - k * (k - 1) / 2 + (l - k);
                float cv = mm[11 + idx] - Sr[k] * Sr[l] * invVf;
                float g = cv / ((n[k] + 1e-8f) * (n[l] + 1e-8f)) * invVf;
                acci += 2.0f * g * g;
            }
        }
        #pragma unroll
        for (int o = 16; o; o >>= 1) acci += __shfl_xor_sync(0xffffffffu, acci, o);
        if (lane == 0) {
            float loss = acci * (1.0f / 90.0f);
            int cc = g_cnt[t];
            float act = (cc >= 1 && V >= 2.0f) ? 1.0f : 0.0f;
            sla[t] = loss * act;
            saf[t] = act;
        }
        __syncwarp();
    }
    __syncthreads();
    if (tid == 0) {
        float s = 0.f;
        #pragma unroll
        for (int b = 0; b < 8; b++) {
            float la = 0.f, af = 0.f;
            #pragma unroll
            for (int c = 0; c < 8; c++) { la += sla[b * 8 + c]; af += saf[b * 8 + c]; }
            s += la / fmaxf(af, 1.0f);
        }
        out[0] = s * 0.125f;
    }
}

// ---------------- launch ----------------
extern "C" void kernel_launch(void* const* d_in, const int* in_sizes, int n_in,
                              void* d_out, int out_size) {
    const float* F  = (const float*)d_in[0];   // feature_map [8,512,96,96]
    const float* P  = (const float*)d_in[1];   // prototypes  [80,512]
    const int*   Mk = (const int*)d_in[2];     // pseudo_mask [8,96,96]
    float* out = (float*)d_out;

    k0_norm_proto<<<81, 128>>>(P);
    k1_sim<<<NPIX / 256, 256>>>(F, Mk);
    k2_fused<<<64 * SEGS, 96>>>(Mk);
    k3<<<1, 1024>>>(out);
}

// round 8
// speedup vs baseline: 1.3656x; 1.3656x over previous
#include <cuda_runtime.h>
#include <cuda_bf16.h>
#include <math.h>

// Problem constants
#define B_   8
#define C_   8
#define K_   10
#define D_   512
#define H_   96
#define W_   96
#define HW_  (H_*W_)          // 9216
#define NPIX (B_*HW_)         // 73728
#define SEGS 12               // k2 segments (8 rows each)

// ---------------- scratch (__device__ globals; no allocations) ----------------
// prototypes packed: g_P2[d2][c*20 + k*2 + parity], row stride 160 floats
__device__ __align__(16) float g_P2[256 * 160];                 // 160 KB
__device__ __align__(16) float g_NumH[(size_t)B_*C_*H_*W_*12];  // 28.3 MB pooled rows
__device__ float g_MomSeg[64 * SEGS * 66];                      // per-(bc,seg) moments
__device__ int   g_cnt[64];                                     // class pixel counts per (b,c)

__constant__ int cPK[45] = {0,0,0,0,0,0,0,0,0, 1,1,1,1,1,1,1,1, 2,2,2,2,2,2,2,
                            3,3,3,3,3,3, 4,4,4,4,4, 5,5,5,5, 6,6,6, 7,7, 8};
__constant__ int cPL[45] = {1,2,3,4,5,6,7,8,9, 2,3,4,5,6,7,8,9, 3,4,5,6,7,8,9,
                            4,5,6,7,8,9, 5,6,7,8,9, 6,7,8,9, 7,8,9, 8,9, 9};

// ---- f32x2 packed helpers ----
__device__ __forceinline__ unsigned long long pk2(float a, float b) {
    unsigned long long r;
    asm("mov.b64 %0, {%1, %2};" : "=l"(r) : "f"(a), "f"(b));
    return r;
}
__device__ __forceinline__ void ffma2(unsigned long long& d, unsigned long long a, unsigned long long b) {
    asm("fma.rn.f32x2 %0, %1, %2, %0;" : "+l"(d) : "l"(a), "l"(b));
}
__device__ __forceinline__ float upsum(unsigned long long v) {
    float lo, hi;
    asm("mov.b64 {%0, %1}, %2;" : "=f"(lo), "=f"(hi) : "l"(v));
    return lo + hi;
}

// ---------------- k0: normalize prototypes into packed layout + zero g_cnt ----------------
__global__ void k0_norm_proto(const float* __restrict__ P) {
    int blk = blockIdx.x;
    int tid = threadIdx.x;          // 128
    if (blk == 80) {
        if (tid < 64) g_cnt[tid] = 0;
        return;
    }
    const float* row = P + blk * D_;
    float ss = 0.f;
    for (int i = tid; i < D_; i += 128) { float v = row[i]; ss = fmaf(v, v, ss); }
    #pragma unroll
    for (int o = 16; o; o >>= 1) ss += __shfl_xor_sync(0xffffffffu, ss, o);
    __shared__ float red[4];
    if ((tid & 31) == 0) red[tid >> 5] = ss;
    __syncthreads();
    float tot = red[0] + red[1] + red[2] + red[3];
    float inv = 1.0f / fmaxf(sqrtf(tot), 1e-12f);
    int c = blk / K_, k = blk % K_;
    for (int d = tid; d < D_; d += 128)
        g_P2[(d >> 1) * 160 + c * 20 + k * 2 + (d & 1)] = row[d] * inv;
}

// ---------------- k1: class-sorted sims + fused horizontal 7-tap pool ----------------
// grid = 256 (8 images x 32 row-triples); block = 288 threads = 3 rows.
__global__ __launch_bounds__(288) void k1_sim(const float* __restrict__ F,
                                              const int* __restrict__ mask) {
    __shared__ __align__(16) float2 sF2[2][8 * 288];   // 36.9 KB: dbl-buf 8 d-pairs x 288 px
    __shared__ __align__(16) float sS[288 * 12];       // 13.8 KB per-pixel sims
    __shared__ short sOrd[288];
    __shared__ unsigned char sCls[288];
    __shared__ int smk[288];
    __shared__ int wcnt[9][9];                          // [warp][class]
    __shared__ int offCM[9][9];                         // [class][warp] exclusive offsets

    int tid = threadIdx.x;
    int blk = blockIdx.x;
    int b = blk >> 5;
    int row0 = (blk & 31) * 3;
    int pin  = row0 * W_ + tid;
    int wi = tid >> 5, ln = tid & 31;

    if (tid < 81) ((int*)wcnt)[tid] = 0;
    int m = mask[b * HW_ + pin];
    smk[tid] = m;
    __syncthreads();

    // stable class sort: warp-level rank via match, then 81-entry scan
    unsigned mmask = __match_any_sync(0xffffffffu, m);
    int rank = __popc(mmask & ((1u << ln) - 1u));
    if ((int)(__ffs(mmask) - 1) == ln) wcnt[wi][m] = __popc(mmask);
    __syncthreads();
    if (tid == 0) {
        int o = 0;
        #pragma unroll
        for (int c = 0; c < 9; c++)
            #pragma unroll
            for (int w = 0; w < 9; w++) { offCM[c][w] = o; o += wcnt[w][c]; }
    }
    __syncthreads();
    int slot = offCM[m][wi] + rank;
    sOrd[slot] = (short)tid;
    sCls[slot] = (unsigned char)m;
    __syncthreads();

    int q  = sOrd[tid];                 // pixel slot this thread computes
    int mq = sCls[tid];
    int cq = (mq > 0) ? (mq - 1) : 0;

    const float* fbt = F + (size_t)b * D_ * HW_ + pin;

    unsigned long long n2 = 0ull;
    unsigned long long s2[10];
    #pragma unroll
    for (int k = 0; k < 10; k++) s2[k] = 0ull;

    float f[16];
    #pragma unroll
    for (int i = 0; i < 16; i++) f[i] = fbt[(size_t)i * HW_];

    for (int ch = 0; ch < 32; ch++) {
        float2* buf = sF2[ch & 1];
        #pragma unroll
        for (int p = 0; p < 8; p++) buf[p * 288 + tid] = make_float2(f[2 * p], f[2 * p + 1]);
        // prefetch next chunk before sync
        if (ch < 31) {
            const float* fn = fbt + (size_t)(ch + 1) * 16 * HW_;
            #pragma unroll
            for (int i = 0; i < 16; i++) f[i] = fn[(size_t)i * HW_];
        }
        __syncthreads();
        int d2b = ch * 8;
        #pragma unroll
        for (int p = 0; p < 8; p++) {
            float2 fv = buf[p * 288 + q];
            unsigned long long f2 = pk2(fv.x, fv.y);
            const ulonglong2* qp =
                (const ulonglong2*)(g_P2 + (size_t)(d2b + p) * 160 + cq * 20);
            ulonglong2 q0 = qp[0], q1 = qp[1], q2 = qp[2], q3 = qp[3], q4 = qp[4];
            ffma2(n2, f2, f2);
            ffma2(s2[0], f2, q0.x); ffma2(s2[1], f2, q0.y);
            ffma2(s2[2], f2, q1.x); ffma2(s2[3], f2, q1.y);
            ffma2(s2[4], f2, q2.x); ffma2(s2[5], f2, q2.y);
            ffma2(s2[6], f2, q3.x); ffma2(s2[7], f2, q3.y);
            ffma2(s2[8], f2, q4.x); ffma2(s2[9], f2, q4.y);
        }
    }

    float nrm = upsum(n2);
    float inv = 1.0f / fmaxf(sqrtf(nrm), 1e-12f);
    {
        float* so = sS + q * 12;
        #pragma unroll
        for (int k = 0; k < 10; k++) so[k] = upsum(s2[k]) * inv;
    }
    __syncthreads();

    // ---- fused horizontal 7-tap class-scattered pool (tid = natural pixel) ----
    int r = tid / 96, w = tid - r * 96;
    int h = row0 + r;
    #pragma unroll
    for (int cc = 0; cc < 8; cc++) {
        float a[11];
        #pragma unroll
        for (int i = 0; i < 11; i++) a[i] = 0.f;
        #pragma unroll
        for (int dw = -3; dw <= 3; dw++) {
            int ww = w + dw;
            if ((unsigned)ww < 96u && smk[r * 96 + ww] == cc + 1) {
                const float* sv = sS + (r * 96 + ww) * 12;
                #pragma unroll
                for (int i = 0; i < 10; i++) a[i] += sv[i];
                a[10] += 1.f;
            }
        }
        float4* o = (float4*)(g_NumH + (size_t)(((b * 8 + cc) * H_ + h) * W_ + w) * 12);
        o[0] = make_float4(a[0], a[1], a[2], a[3]);
        o[1] = make_float4(a[4], a[5], a[6], a[7]);
        o[2] = make_float4(a[8], a[9], a[10], 0.f);
    }
    if (tid < 8) {
        int s = 0;
        #pragma unroll
        for (int w9 = 0; w9 < 9; w9++) s += wcnt[w9][tid + 1];
        atomicAdd(&g_cnt[b * 8 + tid], s);
    }
}

// ---------------- k2b: sliding vertical 7-tap + region + per-(bc,seg) moments ----------------
// grid = 64*SEGS: (bc, seg of 8 rows); block = 96 threads (one per w).
__global__ __launch_bounds__(96) void k2b() {
    int bc  = blockIdx.x / SEGS;
    int seg = blockIdx.x - bc * SEGS;
    int w = threadIdx.x;

    const float* base = g_NumH + (size_t)bc * HW_ * 12 + (size_t)w * 12;

    float vs[11];
    #pragma unroll
    for (int i = 0; i < 11; i++) vs[i] = 0.f;

    auto acc = [&](int hh, float sg) {
        const float4* rr = (const float4*)(base + (size_t)hh * (W_ * 12));
        float4 x = rr[0], y = rr[1], z = rr[2];
        vs[0] = fmaf(sg, x.x, vs[0]); vs[1] = fmaf(sg, x.y, vs[1]);
        vs[2] = fmaf(sg, x.z, vs[2]); vs[3] = fmaf(sg, x.w, vs[3]);
        vs[4] = fmaf(sg, y.x, vs[4]); vs[5] = fmaf(sg, y.y, vs[5]);
        vs[6] = fmaf(sg, y.z, vs[6]); vs[7] = fmaf(sg, y.w, vs[7]);
        vs[8] = fmaf(sg, z.x, vs[8]); vs[9] = fmaf(sg, z.y, vs[9]);
        vs[10] = fmaf(sg, z.z, vs[10]);
    };

    int h0 = seg * 8;
    #pragma unroll
    for (int hh = h0 - 3; hh < h0 + 3; hh++)
        if (hh >= 0) acc(hh, 1.f);

    float V = 0.f;
    float Sr[10]; float M[55];
    #pragma unroll
    for (int k = 0; k < 10; k++) Sr[k] = 0.f;
    #pragma unroll
    for (int i = 0; i < 55; i++) M[i] = 0.f;

    #pragma unroll
    for (int h = h0; h < h0 + 8; h++) {
        if (h + 3 < 96) acc(h + 3, 1.f);
        float den = vs[10] * (1.0f / 49.0f);
        if (den > 0.05f) {
            float inv = 1.0f / (den + 1e-8f);
            float r[10];
            #pragma unroll
            for (int k = 0; k < 10; k++) r[k] = (vs[k] * (1.0f / 49.0f)) * inv;
            V += 1.f;
            #pragma unroll
            for (int k = 0; k < 10; k++) Sr[k] += r[k];
            int idx = 0;
            #pragma unroll
            for (int k = 0; k < 10; k++)
                #pragma unroll
                for (int l = k; l < 10; l++) { M[idx] = fmaf(r[k], r[l], M[idx]); idx++; }
        }
        if (h - 3 >= 0) acc(h - 3, -1.f);
    }

    // warp butterfly reduce (3 warps, same (bc,seg))
    #pragma unroll
    for (int o = 16; o; o >>= 1) V += __shfl_xor_sync(0xffffffffu, V, o);
    #pragma unroll
    for (int k = 0; k < 10; k++) {
        float v = Sr[k];
        #pragma unroll
        for (int o = 16; o; o >>= 1) v += __shfl_xor_sync(0xffffffffu, v, o);
        Sr[k] = v;
    }
    #pragma unroll
    for (int i = 0; i < 55; i++) {
        float v = M[i];
        #pragma unroll
        for (int o = 16; o; o >>= 1) v += __shfl_xor_sync(0xffffffffu, v, o);
        M[i] = v;
    }
    __shared__ float red[3][66];
    int lane = w & 31, wid = w >> 5;
    if (lane == 0) {
        red[wid][0] = V;
        #pragma unroll
        for (int k = 0; k < 10; k++) red[wid][1 + k] = Sr[k];
        #pragma unroll
        for (int i = 0; i < 55; i++) red[wid][11 + i] = M[i];
    }
    __syncthreads();
    if (w < 66)
        g_MomSeg[(size_t)blockIdx.x * 66 + w] = red[0][w] + red[1][w] + red[2][w];
}

// ---------------- k3: finalize scalar (1 block, 32 warps; warp per 2 bc) ----------------
__global__ __launch_bounds__(1024) void k3(float* __restrict__ out) {
    __shared__ float sM[64][66];
    __shared__ float sla[64], saf[64];
    int tid = threadIdx.x;
    int wi = tid >> 5, lane = tid & 31;

    #pragma unroll
    for (int t = wi * 2; t < wi * 2 + 2; t++) {
        for (int i = lane; i < 66; i += 32) {
            float s = 0.f;
            #pragma unroll
            for (int seg = 0; seg < SEGS; seg++) s += g_MomSeg[(size_t)(t * SEGS + seg) * 66 + i];
            sM[t][i] = s;
        }
        __syncwarp();
        const float* mm = sM[t];
        float V = mm[0];
        float Vf = fmaxf(V, 1.0f);
        float invVf = 1.0f / Vf;

        float Srk = 0.f, nk = 0.f;
        if (lane < 10) {
            Srk = mm[1 + lane];
            int di = 10 * lane - lane * (lane - 1) / 2;
            float cv = mm[11 + di] - Srk * Srk * invVf;
            nk = sqrtf(fmaxf(cv, 0.f));
        }
        float Sr[10], n[10];
        #pragma unroll
        for (int k = 0; k < 10; k++) {
            Sr[k] = __shfl_sync(0xffffffffu, Srk, k);
            n[k]  = __shfl_sync(0xffffffffu, nk, k);
        }
        float acci = 0.f;
        #pragma unroll
        for (int rep = 0; rep < 2; rep++) {
            int p = lane + rep * 32;
            if (p < 45) {
                int k = cPK[p], l = cPL[p];
                int idx = 10 * k - k * (k - 1) / 2 + (l - k);
                float cv = mm[11 + idx] - Sr[k] * Sr[l] * invVf;
                float g = cv / ((n[k] + 1e-8f) * (n[l] + 1e-8f)) * invVf;
                acci += 2.0f * g * g;
            }
        }
        #pragma unroll
        for (int o = 16; o; o >>= 1) acci += __shfl_xor_sync(0xffffffffu, acci, o);
        if (lane == 0) {
            float loss = acci * (1.0f / 90.0f);
            int cc = g_cnt[t];
            float act = (cc >= 1 && V >= 2.0f) ? 1.0f : 0.0f;
            sla[t] = loss * act;
            saf[t] = act;
        }
        __syncwarp();
    }
    __syncthreads();
    if (tid == 0) {
        float s = 0.f;
        #pragma unroll
        for (int b = 0; b < 8; b++) {
            float la = 0.f, af = 0.f;
            #pragma unroll
            for (int c = 0; c < 8; c++) { la += sla[b * 8 + c]; af += saf[b * 8 + c]; }
            s += la / fmaxf(af, 1.0f);
        }
        out[0] = s * 0.125f;
    }
}

// ---------------- launch ----------------
extern "C" void kernel_launch(void* const* d_in, const int* in_sizes, int n_in,
                              void* d_out, int out_size) {
    const float* F  = (const float*)d_in[0];   // feature_map [8,512,96,96]
    const float* P  = (const float*)d_in[1];   // prototypes  [80,512]
    const int*   Mk = (const int*)d_in[2];     // pseudo_mask [8,96,96]
    float* out = (float*)d_out;

    k0_norm_proto<<<81, 128>>>(P);
    k1_sim<<<256, 288>>>(F, Mk);
    k2b<<<64 * SEGS, 96>>>();
    k3<<<1, 1024>>>(out);
}

// round 9
// speedup vs baseline: 1.6605x; 1.2159x over previous
#include <cuda_runtime.h>
#include <cuda_bf16.h>
#include <math.h>

// Problem constants
#define B_   8
#define C_   8
#define K_   10
#define D_   512
#define H_   96
#define W_   96
#define HW_  (H_*W_)          // 9216
#define NPIX (B_*HW_)         // 73728
#define DS_  4                // d splits
#define DPS_ 128              // d per split
#define SEGS 12               // k2 segments (8 rows each)

// ---------------- scratch (__device__ globals; no allocations) ----------------
// prototypes in d-pair packed layout: g_P2[d2][c*28 + k*2 + parity]
__device__ __align__(16) float g_P2[256 * 224];                     // 229 KB
__device__ __align__(16) float g_part[(size_t)DS_ * NPIX * 12];     // 14.2 MB partial dots
__device__ __align__(16) float g_NumH[(size_t)B_*C_*H_*W_*12];      // 28.3 MB
__device__ float g_MomSeg[64 * SEGS * 66];                          // per-(bc,seg) moments
__device__ int   g_cnt[64];                                         // class pixel counts per (b,c)

__constant__ int cPK[45] = {0,0,0,0,0,0,0,0,0, 1,1,1,1,1,1,1,1, 2,2,2,2,2,2,2,
                            3,3,3,3,3,3, 4,4,4,4,4, 5,5,5,5, 6,6,6, 7,7, 8};
__constant__ int cPL[45] = {1,2,3,4,5,6,7,8,9, 2,3,4,5,6,7,8,9, 3,4,5,6,7,8,9,
                            4,5,6,7,8,9, 5,6,7,8,9, 6,7,8,9, 7,8,9, 8,9, 9};

// ---- f32x2 packed helpers ----
__device__ __forceinline__ unsigned long long pk2(float a, float b) {
    unsigned long long r;
    asm("mov.b64 %0, {%1, %2};" : "=l"(r) : "f"(a), "f"(b));
    return r;
}
__device__ __forceinline__ void ffma2(unsigned long long& d, unsigned long long a, unsigned long long b) {
    asm("fma.rn.f32x2 %0, %1, %2, %0;" : "+l"(d) : "l"(a), "l"(b));
}
__device__ __forceinline__ float upsum(unsigned long long v) {
    float lo, hi;
    asm("mov.b64 {%0, %1}, %2;" : "=f"(lo), "=f"(hi) : "l"(v));
    return lo + hi;
}

// ---------------- kz: zero g_cnt ----------------
__global__ void kz() {
    if (threadIdx.x < 64) g_cnt[threadIdx.x] = 0;
}

// ---------------- kd: pad launch so k1 lands at ncu capture slot #3 ----------------
__global__ void kd() {}

// ---------------- k0: normalize prototypes into packed pair layout ----------------
__global__ void k0_norm_proto(const float* __restrict__ P) {
    int blk = blockIdx.x;
    int tid = threadIdx.x;          // 128
    const float* row = P + blk * D_;
    float ss = 0.f;
    for (int i = tid; i < D_; i += 128) { float v = row[i]; ss = fmaf(v, v, ss); }
    #pragma unroll
    for (int o = 16; o; o >>= 1) ss += __shfl_xor_sync(0xffffffffu, ss, o);
    __shared__ float red[4];
    if ((tid & 31) == 0) red[tid >> 5] = ss;
    __syncthreads();
    float tot = red[0] + red[1] + red[2] + red[3];
    float inv = 1.0f / fmaxf(sqrtf(tot), 1e-12f);
    int c = blk / K_, k = blk % K_;
    for (int d = tid; d < D_; d += 128)
        g_P2[(d >> 1) * 224 + c * 28 + k * 2 + (d & 1)] = row[d] * inv;
}

// ---------------- k1: partial sims over a 128-d slice (FFMA2 packed) ----------------
// grid = 1024: blk = ds*256 + (b*32 + rowtriple); block = 288 threads = 3 rows.
__global__ __launch_bounds__(288) void k1_sim(const float* __restrict__ F,
                                              const int* __restrict__ mask) {
    __shared__ __align__(16) float sp[32 * 224];   // 28 KB: 32 d2-rows of packed protos

    int tid = threadIdx.x;
    int blk = blockIdx.x;
    int ds  = blk >> 8;
    int sub = blk & 255;
    int b = sub >> 5;
    int row0 = (sub & 31) * 3;
    int pin  = row0 * W_ + tid;
    int pixg = b * HW_ + pin;

    int m = mask[pixg];
    int c = (m > 0) ? (m - 1) : 0;

    const float* fb = F + ((size_t)b * D_ + ds * DPS_) * HW_ + pin;

    unsigned long long n2 = 0ull;
    unsigned long long s2[10];
    #pragma unroll
    for (int k = 0; k < 10; k++) s2[k] = 0ull;

    for (int ch = 0; ch < 2; ch++) {
        __syncthreads();
        const float4* src = (const float4*)(g_P2 + (size_t)(ds * 64 + ch * 32) * 224);
        float4* dst = (float4*)sp;
        for (int i = tid; i < 32 * 224 / 4; i += 288) dst[i] = src[i];
        __syncthreads();

        const float* fp = fb + (size_t)ch * 64 * HW_;
        #pragma unroll 2
        for (int i2 = 0; i2 < 32; i2 += 4) {
            float f[8];
            #pragma unroll
            for (int j = 0; j < 8; j++) f[j] = fp[(size_t)(i2 * 2 + j) * HW_];
            #pragma unroll
            for (int j2 = 0; j2 < 4; j2++) {
                unsigned long long f2 = pk2(f[2 * j2], f[2 * j2 + 1]);
                const ulonglong2* q = (const ulonglong2*)(sp + (i2 + j2) * 224 + c * 28);
                ulonglong2 q0 = q[0], q1 = q[1], q2 = q[2], q3 = q[3], q4 = q[4];
                ffma2(n2, f2, f2);
                ffma2(s2[0], f2, q0.x); ffma2(s2[1], f2, q0.y);
                ffma2(s2[2], f2, q1.x); ffma2(s2[3], f2, q1.y);
                ffma2(s2[4], f2, q2.x); ffma2(s2[5], f2, q2.y);
                ffma2(s2[6], f2, q3.x); ffma2(s2[7], f2, q3.y);
                ffma2(s2[8], f2, q4.x); ffma2(s2[9], f2, q4.y);
            }
        }
    }
    float4* o = (float4*)(g_part + ((size_t)ds * NPIX + pixg) * 12);
    o[0] = make_float4(upsum(s2[0]), upsum(s2[1]), upsum(s2[2]), upsum(s2[3]));
    o[1] = make_float4(upsum(s2[4]), upsum(s2[5]), upsum(s2[6]), upsum(s2[7]));
    o[2] = make_float4(upsum(s2[8]), upsum(s2[9]), upsum(n2), 0.f);
}

// ---------------- k1b: merge partials + normalize + horizontal 7-tap pool ----------------
// grid = 768 (b,h); block = 96 threads (one per w).
__global__ __launch_bounds__(96) void k1b(const int* __restrict__ mask) {
    __shared__ __align__(16) float sS[96 * 12];
    __shared__ int smask[96];
    __shared__ int hist[8];

    int bh = blockIdx.x;
    int b = bh / H_, h = bh - b * H_;
    int w = threadIdx.x;
    int pixg = b * HW_ + h * W_ + w;

    if (w < 8) hist[w] = 0;
    int m = mask[pixg];
    smask[w] = m;
    __syncthreads();
    if (m > 0) atomicAdd(&hist[m - 1], 1);

    float a[11];
    #pragma unroll
    for (int i = 0; i < 11; i++) a[i] = 0.f;
    #pragma unroll
    for (int ds = 0; ds < DS_; ds++) {
        const float4* p = (const float4*)(g_part + ((size_t)ds * NPIX + pixg) * 12);
        float4 x = p[0], y = p[1], z = p[2];
        a[0]+=x.x; a[1]+=x.y; a[2]+=x.z; a[3]+=x.w;
        a[4]+=y.x; a[5]+=y.y; a[6]+=y.z; a[7]+=y.w;
        a[8]+=z.x; a[9]+=z.y; a[10]+=z.z;
    }
    float inv = 1.0f / fmaxf(sqrtf(a[10]), 1e-12f);
    float* so = sS + w * 12;
    #pragma unroll
    for (int k = 0; k < 10; k++) so[k] = a[k] * inv;
    so[10] = 0.f; so[11] = 0.f;
    __syncthreads();

    // horizontal 7-tap class-scattered pool
    #pragma unroll
    for (int cc = 0; cc < 8; cc++) {
        float s[11];
        #pragma unroll
        for (int i = 0; i < 11; i++) s[i] = 0.f;
        #pragma unroll
        for (int dw = -3; dw <= 3; dw++) {
            int ww = w + dw;
            if ((unsigned)ww < 96u && smask[ww] == cc + 1) {
                const float4* sv = (const float4*)(sS + (size_t)ww * 12);
                float4 x = sv[0], y = sv[1], z = sv[2];
                s[0]+=x.x; s[1]+=x.y; s[2]+=x.z; s[3]+=x.w;
                s[4]+=y.x; s[5]+=y.y; s[6]+=y.z; s[7]+=y.w;
                s[8]+=z.x; s[9]+=z.y; s[10]+=1.f;
            }
        }
        float4* o = (float4*)(g_NumH + (size_t)(((b * 8 + cc) * H_ + h) * W_ + w) * 12);
        o[0] = make_float4(s[0], s[1], s[2], s[3]);
        o[1] = make_float4(s[4], s[5], s[6], s[7]);
        o[2] = make_float4(s[8], s[9], s[10], 0.f);
    }
    if (w < 8) atomicAdd(&g_cnt[b * 8 + w], hist[w]);
}

// ---------------- k2b: sliding vertical 7-tap + region + per-(bc,seg) moments ----------------
// grid = 64*SEGS: (bc, seg of 8 rows); block = 96 threads (one per w).
__global__ __launch_bounds__(96) void k2b() {
    int bc  = blockIdx.x / SEGS;
    int seg = blockIdx.x - bc * SEGS;
    int w = threadIdx.x;

    const float* base = g_NumH + (size_t)bc * HW_ * 12 + (size_t)w * 12;

    float vs[11];
    #pragma unroll
    for (int i = 0; i < 11; i++) vs[i] = 0.f;

    auto acc = [&](int hh, float sg) {
        const float4* rr = (const float4*)(base + (size_t)hh * (W_ * 12));
        float4 x = rr[0], y = rr[1], z = rr[2];
        vs[0] = fmaf(sg, x.x, vs[0]); vs[1] = fmaf(sg, x.y, vs[1]);
        vs[2] = fmaf(sg, x.z, vs[2]); vs[3] = fmaf(sg, x.w, vs[3]);
        vs[4] = fmaf(sg, y.x, vs[4]); vs[5] = fmaf(sg, y.y, vs[5]);
        vs[6] = fmaf(sg, y.z, vs[6]); vs[7] = fmaf(sg, y.w, vs[7]);
        vs[8] = fmaf(sg, z.x, vs[8]); vs[9] = fmaf(sg, z.y, vs[9]);
        vs[10] = fmaf(sg, z.z, vs[10]);
    };

    int h0 = seg * 8;
    #pragma unroll
    for (int hh = h0 - 3; hh < h0 + 3; hh++)
        if (hh >= 0) acc(hh, 1.f);

    float V = 0.f;
    float Sr[10]; float M[55];
    #pragma unroll
    for (int k = 0; k < 10; k++) Sr[k] = 0.f;
    #pragma unroll
    for (int i = 0; i < 55; i++) M[i] = 0.f;

    #pragma unroll
    for (int h = h0; h < h0 + 8; h++) {
        if (h + 3 < 96) acc(h + 3, 1.f);
        float den = vs[10] * (1.0f / 49.0f);
        if (den > 0.05f) {
            float inv = 1.0f / (den + 1e-8f);
            float r[10];
            #pragma unroll
            for (int k = 0; k < 10; k++) r[k] = (vs[k] * (1.0f / 49.0f)) * inv;
            V += 1.f;
            #pragma unroll
            for (int k = 0; k < 10; k++) Sr[k] += r[k];
            int idx = 0;
            #pragma unroll
            for (int k = 0; k < 10; k++)
                #pragma unroll
                for (int l = k; l < 10; l++) { M[idx] = fmaf(r[k], r[l], M[idx]); idx++; }
        }
        if (h - 3 >= 0) acc(h - 3, -1.f);
    }

    // warp butterfly reduce (3 warps, same (bc,seg))
    #pragma unroll
    for (int o = 16; o; o >>= 1) V += __shfl_xor_sync(0xffffffffu, V, o);
    #pragma unroll
    for (int k = 0; k < 10; k++) {
        float v = Sr[k];
        #pragma unroll
        for (int o = 16; o; o >>= 1) v += __shfl_xor_sync(0xffffffffu, v, o);
        Sr[k] = v;
    }
    #pragma unroll
    for (int i = 0; i < 55; i++) {
        float v = M[i];
        #pragma unroll
        for (int o = 16; o; o >>= 1) v += __shfl_xor_sync(0xffffffffu, v, o);
        M[i] = v;
    }
    __shared__ float red[3][66];
    int lane = w & 31, wid = w >> 5;
    if (lane == 0) {
        red[wid][0] = V;
        #pragma unroll
        for (int k = 0; k < 10; k++) red[wid][1 + k] = Sr[k];
        #pragma unroll
        for (int i = 0; i < 55; i++) red[wid][11 + i] = M[i];
    }
    __syncthreads();
    if (w < 66)
        g_MomSeg[(size_t)blockIdx.x * 66 + w] = red[0][w] + red[1][w] + red[2][w];
}

// ---------------- k3: finalize scalar (1 block, 32 warps; warp per 2 bc) ----------------
__global__ __launch_bounds__(1024) void k3(float* __restrict__ out) {
    __shared__ float sM[64][66];
    __shared__ float sla[64], saf[64];
    int tid = threadIdx.x;
    int wi = tid >> 5, lane = tid & 31;

    #pragma unroll
    for (int t = wi * 2; t < wi * 2 + 2; t++) {
        for (int i = lane; i < 66; i += 32) {
            float s = 0.f;
            #pragma unroll
            for (int seg = 0; seg < SEGS; seg++) s += g_MomSeg[(size_t)(t * SEGS + seg) * 66 + i];
            sM[t][i] = s;
        }
        __syncwarp();
        const float* mm = sM[t];
        float V = mm[0];
        float Vf = fmaxf(V, 1.0f);
        float invVf = 1.0f / Vf;

        float Srk = 0.f, nk = 0.f;
        if (lane < 10) {
            Srk = mm[1 + lane];
            int di = 10 * lane - lane * (lane - 1) / 2;
            float cv = mm[11 + di] - Srk * Srk * invVf;
            nk = sqrtf(fmaxf(cv, 0.f));
        }
        float Sr[10], n[10];
        #pragma unroll
        for (int k = 0; k < 10; k++) {
            Sr[k] = __shfl_sync(0xffffffffu, Srk, k);
            n[k]  = __shfl_sync(0xffffffffu, nk, k);
        }
        float acci = 0.f;
        #pragma unroll
        for (int rep = 0; rep < 2; rep++) {
            int p = lane + rep * 32;
            if (p < 45) {
                int k = cPK[p], l = cPL[p];
                int idx = 10 * k - k * (k - 1) / 2 + (l - k);
                float cv = mm[11 + idx] - Sr[k] * Sr[l] * invVf;
                float g = cv / ((n[k] + 1e-8f) * (n[l] + 1e-8f)) * invVf;
                acci += 2.0f * g * g;
            }
        }
        #pragma unroll
        for (int o = 16; o; o >>= 1) acci += __shfl_xor_sync(0xffffffffu, acci, o);
        if (lane == 0) {
            float loss = acci * (1.0f / 90.0f);
            int cc = g_cnt[t];
            float act = (cc >= 1 && V >= 2.0f) ? 1.0f : 0.0f;
            sla[t] = loss * act;
            saf[t] = act;
        }
        __syncwarp();
    }
    __syncthreads();
    if (tid == 0) {
        float s = 0.f;
        #pragma unroll
        for (int b = 0; b < 8; b++) {
            float la = 0.f, af = 0.f;
            #pragma unroll
            for (int c = 0; c < 8; c++) { la += sla[b * 8 + c]; af += saf[b * 8 + c]; }
            s += la / fmaxf(af, 1.0f);
        }
        out[0] = s * 0.125f;
    }
}

// ---------------- launch ----------------
extern "C" void kernel_launch(void* const* d_in, const int* in_sizes, int n_in,
                              void* d_out, int out_size) {
    const float* F  = (const float*)d_in[0];   // feature_map [8,512,96,96]
    const float* P  = (const float*)d_in[1];   // prototypes  [80,512]
    const int*   Mk = (const int*)d_in[2];     // pseudo_mask [8,96,96]
    float* out = (float*)d_out;

    kz<<<1, 64>>>();                  // #0
    k0_norm_proto<<<80, 128>>>(P);    // #1
    kd<<<1, 32>>>();                  // #2 pad: put k1 at ncu capture slot #3
    k1_sim<<<1024, 288>>>(F, Mk);     // #3  <-- profiled
    k1b<<<768, 96>>>(Mk);             // #4
    k2b<<<64 * SEGS, 96>>>();         // #5
    k3<<<1, 1024>>>(out);             // #6
}

// round 12
// speedup vs baseline: 2.0375x; 1.2271x over previous
#include <cuda_runtime.h>
#include <cuda_bf16.h>
#include <math.h>

// Problem constants
#define B_   8
#define C_   8
#define K_   10
#define D_   512
#define H_   96
#define W_   96
#define HW_  (H_*W_)          // 9216
#define NPIX (B_*HW_)         // 73728
#define DS_  4                // d splits
#define DPS_ 128              // d per split
#define SEGS 12               // k2 segments (8 rows each)

// ---------------- scratch (__device__ globals; no allocations) ----------------
// prototypes in d-pair packed layout: g_P2[d2][c*28 + k*2 + parity]
__device__ __align__(16) float g_P2[256 * 224];                     // 229 KB
__device__ __align__(16) float g_part[(size_t)DS_ * NPIX * 12];     // 14.2 MB partial dots
__device__ __align__(16) float g_NumH[(size_t)B_*C_*H_*W_*12];      // 28.3 MB
__device__ float g_MomSeg[64 * SEGS * 66];                          // per-(bc,seg) moments
__device__ int   g_cnt[64];                                         // class pixel counts per (b,c)

__constant__ int cPK[45] = {0,0,0,0,0,0,0,0,0, 1,1,1,1,1,1,1,1, 2,2,2,2,2,2,2,
                            3,3,3,3,3,3, 4,4,4,4,4, 5,5,5,5, 6,6,6, 7,7, 8};
__constant__ int cPL[45] = {1,2,3,4,5,6,7,8,9, 2,3,4,5,6,7,8,9, 3,4,5,6,7,8,9,
                            4,5,6,7,8,9, 5,6,7,8,9, 6,7,8,9, 7,8,9, 8,9, 9};

// ---- f32x2 packed helpers ----
__device__ __forceinline__ unsigned long long pk2(float a, float b) {
    unsigned long long r;
    asm("mov.b64 %0, {%1, %2};" : "=l"(r) : "f"(a), "f"(b));
    return r;
}
__device__ __forceinline__ void ffma2(unsigned long long& d, unsigned long long a, unsigned long long b) {
    asm("fma.rn.f32x2 %0, %1, %2, %0;" : "+l"(d) : "l"(a), "l"(b));
}
__device__ __forceinline__ float upsum(unsigned long long v) {
    float lo, hi;
    asm("mov.b64 {%0, %1}, %2;" : "=f"(lo), "=f"(hi) : "l"(v));
    return lo + hi;
}

// ---------------- k0: normalize prototypes into packed pair layout + zero g_cnt ----------------
__global__ void k0_norm_proto(const float* __restrict__ P) {
    int blk = blockIdx.x;
    int tid = threadIdx.x;          // 128
    if (blk == 80) {                // zero replay-state scratch
        if (tid < 64) g_cnt[tid] = 0;
        return;
    }
    const float* row = P + blk * D_;
    float ss = 0.f;
    for (int i = tid; i < D_; i += 128) { float v = row[i]; ss = fmaf(v, v, ss); }
    #pragma unroll
    for (int o = 16; o; o >>= 1) ss += __shfl_xor_sync(0xffffffffu, ss, o);
    __shared__ float red[4];
    if ((tid & 31) == 0) red[tid >> 5] = ss;
    __syncthreads();
    float tot = red[0] + red[1] + red[2] + red[3];
    float inv = 1.0f / fmaxf(sqrtf(tot), 1e-12f);
    int c = blk / K_, k = blk % K_;
    for (int d = tid; d < D_; d += 128)
        g_P2[(d >> 1) * 224 + c * 28 + k * 2 + (d & 1)] = row[d] * inv;
}

// ---------------- k1: partial sims over a 128-d slice (FFMA2 packed) ----------------
// grid = 1024: blk = ds*256 + (b*32 + rowtriple); block = 288 threads = 3 rows.
// __launch_bounds__(288, 4): cap regs at 56 -> 4 blocks/SM (occ 38.6% -> ~51%).
__global__ __launch_bounds__(288, 4) void k1_sim(const float* __restrict__ F,
                                                 const int* __restrict__ mask) {
    __shared__ __align__(16) float sp[32 * 224];   // 28 KB: 32 d2-rows of packed protos

    int tid = threadIdx.x;
    int blk = blockIdx.x;
    int ds  = blk >> 8;
    int sub = blk & 255;
    int b = sub >> 5;
    int row0 = (sub & 31) * 3;
    int pin  = row0 * W_ + tid;
    int pixg = b * HW_ + pin;

    int m = mask[pixg];
    int c = (m > 0) ? (m - 1) : 0;

    const float* fb = F + ((size_t)b * D_ + ds * DPS_) * HW_ + pin;

    unsigned long long n2 = 0ull;
    unsigned long long s2[10];
    #pragma unroll
    for (int k = 0; k < 10; k++) s2[k] = 0ull;

    for (int ch = 0; ch < 2; ch++) {
        __syncthreads();
        const float4* src = (const float4*)(g_P2 + (size_t)(ds * 64 + ch * 32) * 224);
        float4* dst = (float4*)sp;
        for (int i = tid; i < 32 * 224 / 4; i += 288) dst[i] = src[i];
        __syncthreads();

        const float* fp = fb + (size_t)ch * 64 * HW_;
        #pragma unroll 2
        for (int i2 = 0; i2 < 32; i2 += 4) {
            float f[8];
            #pragma unroll
            for (int j = 0; j < 8; j++) f[j] = fp[(size_t)(i2 * 2 + j) * HW_];
            #pragma unroll
            for (int j2 = 0; j2 < 4; j2++) {
                unsigned long long f2 = pk2(f[2 * j2], f[2 * j2 + 1]);
                const ulonglong2* q = (const ulonglong2*)(sp + (i2 + j2) * 224 + c * 28);
                ulonglong2 q0 = q[0], q1 = q[1], q2 = q[2], q3 = q[3], q4 = q[4];
                ffma2(n2, f2, f2);
                ffma2(s2[0], f2, q0.x); ffma2(s2[1], f2, q0.y);
                ffma2(s2[2], f2, q1.x); ffma2(s2[3], f2, q1.y);
                ffma2(s2[4], f2, q2.x); ffma2(s2[5], f2, q2.y);
                ffma2(s2[6], f2, q3.x); ffma2(s2[7], f2, q3.y);
                ffma2(s2[8], f2, q4.x); ffma2(s2[9], f2, q4.y);
            }
        }
    }
    float4* o = (float4*)(g_part + ((size_t)ds * NPIX + pixg) * 12);
    o[0] = make_float4(upsum(s2[0]), upsum(s2[1]), upsum(s2[2]), upsum(s2[3]));
    o[1] = make_float4(upsum(s2[4]), upsum(s2[5]), upsum(s2[6]), upsum(s2[7]));
    o[2] = make_float4(upsum(s2[8]), upsum(s2[9]), upsum(n2), 0.f);
}

// ---------------- k1b: merge partials + normalize + horizontal 7-tap pool ----------------
// grid = 768 (b,h); block = 96 threads (one per w).
__global__ __launch_bounds__(96) void k1b(const int* __restrict__ mask) {
    __shared__ __align__(16) float sS[96 * 12];
    __shared__ int smask[96];
    __shared__ int hist[8];

    int bh = blockIdx.x;
    int b = bh / H_, h = bh - b * H_;
    int w = threadIdx.x;
    int pixg = b * HW_ + h * W_ + w;

    if (w < 8) hist[w] = 0;
    int m = mask[pixg];
    smask[w] = m;
    __syncthreads();
    if (m > 0) atomicAdd(&hist[m - 1], 1);

    float a[11];
    #pragma unroll
    for (int i = 0; i < 11; i++) a[i] = 0.f;
    #pragma unroll
    for (int ds = 0; ds < DS_; ds++) {
        const float4* p = (const float4*)(g_part + ((size_t)ds * NPIX + pixg) * 12);
        float4 x = p[0], y = p[1], z = p[2];
        a[0]+=x.x; a[1]+=x.y; a[2]+=x.z; a[3]+=x.w;
        a[4]+=y.x; a[5]+=y.y; a[6]+=y.z; a[7]+=y.w;
        a[8]+=z.x; a[9]+=z.y; a[10]+=z.z;
    }
    float inv = 1.0f / fmaxf(sqrtf(a[10]), 1e-12f);
    float* so = sS + w * 12;
    #pragma unroll
    for (int k = 0; k < 10; k++) so[k] = a[k] * inv;
    so[10] = 0.f; so[11] = 0.f;
    __syncthreads();

    // horizontal 7-tap class-scattered pool
    #pragma unroll
    for (int cc = 0; cc < 8; cc++) {
        float s[11];
        #pragma unroll
        for (int i = 0; i < 11; i++) s[i] = 0.f;
        #pragma unroll
        for (int dw = -3; dw <= 3; dw++) {
            int ww = w + dw;
            if ((unsigned)ww < 96u && smask[ww] == cc + 1) {
                const float4* sv = (const float4*)(sS + (size_t)ww * 12);
                float4 x = sv[0], y = sv[1], z = sv[2];
                s[0]+=x.x; s[1]+=x.y; s[2]+=x.z; s[3]+=x.w;
                s[4]+=y.x; s[5]+=y.y; s[6]+=y.z; s[7]+=y.w;
                s[8]+=z.x; s[9]+=z.y; s[10]+=1.f;
            }
        }
        float4* o = (float4*)(g_NumH + (size_t)(((b * 8 + cc) * H_ + h) * W_ + w) * 12);
        o[0] = make_float4(s[0], s[1], s[2], s[3]);
        o[1] = make_float4(s[4], s[5], s[6], s[7]);
        o[2] = make_float4(s[8], s[9], s[10], 0.f);
    }
    if (w < 8) atomicAdd(&g_cnt[b * 8 + w], hist[w]);
}

// ---------------- k2b: sliding vertical 7-tap + region + per-(bc,seg) moments ----------------
// grid = 64*SEGS: (bc, seg of 8 rows); block = 96 threads (one per w).
__global__ __launch_bounds__(96) void k2b() {
    int bc  = blockIdx.x / SEGS;
    int seg = blockIdx.x - bc * SEGS;
    int w = threadIdx.x;

    const float* base = g_NumH + (size_t)bc * HW_ * 12 + (size_t)w * 12;

    float vs[11];
    #pragma unroll
    for (int i = 0; i < 11; i++) vs[i] = 0.f;

    auto acc = [&](int hh, float sg) {
        const float4* rr = (const float4*)(base + (size_t)hh * (W_ * 12));
        float4 x = rr[0], y = rr[1], z = rr[2];
        vs[0] = fmaf(sg, x.x, vs[0]); vs[1] = fmaf(sg, x.y, vs[1]);
        vs[2] = fmaf(sg, x.z, vs[2]); vs[3] = fmaf(sg, x.w, vs[3]);
        vs[4] = fmaf(sg, y.x, vs[4]); vs[5] = fmaf(sg, y.y, vs[5]);
        vs[6] = fmaf(sg, y.z, vs[6]); vs[7] = fmaf(sg, y.w, vs[7]);
        vs[8] = fmaf(sg, z.x, vs[8]); vs[9] = fmaf(sg, z.y, vs[9]);
        vs[10] = fmaf(sg, z.z, vs[10]);
    };

    int h0 = seg * 8;
    #pragma unroll
    for (int hh = h0 - 3; hh < h0 + 3; hh++)
        if (hh >= 0) acc(hh, 1.f);

    float V = 0.f;
    float Sr[10]; float M[55];
    #pragma unroll
    for (int k = 0; k < 10; k++) Sr[k] = 0.f;
    #pragma unroll
    for (int i = 0; i < 55; i++) M[i] = 0.f;

    #pragma unroll
    for (int h = h0; h < h0 + 8; h++) {
        if (h + 3 < 96) acc(h + 3, 1.f);
        float den = vs[10] * (1.0f / 49.0f);
        if (den > 0.05f) {
            float inv = 1.0f / (den + 1e-8f);
            float r[10];
            #pragma unroll
            for (int k = 0; k < 10; k++) r[k] = (vs[k] * (1.0f / 49.0f)) * inv;
            V += 1.f;
            #pragma unroll
            for (int k = 0; k < 10; k++) Sr[k] += r[k];
            int idx = 0;
            #pragma unroll
            for (int k = 0; k < 10; k++)
                #pragma unroll
                for (int l = k; l < 10; l++) { M[idx] = fmaf(r[k], r[l], M[idx]); idx++; }
        }
        if (h - 3 >= 0) acc(h - 3, -1.f);
    }

    // warp butterfly reduce (3 warps, same (bc,seg))
    #pragma unroll
    for (int o = 16; o; o >>= 1) V += __shfl_xor_sync(0xffffffffu, V, o);
    #pragma unroll
    for (int k = 0; k < 10; k++) {
        float v = Sr[k];
        #pragma unroll
        for (int o = 16; o; o >>= 1) v += __shfl_xor_sync(0xffffffffu, v, o);
        Sr[k] = v;
    }
    #pragma unroll
    for (int i = 0; i < 55; i++) {
        float v = M[i];
        #pragma unroll
        for (int o = 16; o; o >>= 1) v += __shfl_xor_sync(0xffffffffu, v, o);
        M[i] = v;
    }
    __shared__ float red[3][66];
    int lane = w & 31, wid = w >> 5;
    if (lane == 0) {
        red[wid][0] = V;
        #pragma unroll
        for (int k = 0; k < 10; k++) red[wid][1 + k] = Sr[k];
        #pragma unroll
        for (int i = 0; i < 55; i++) red[wid][11 + i] = M[i];
    }
    __syncthreads();
    if (w < 66)
        g_MomSeg[(size_t)blockIdx.x * 66 + w] = red[0][w] + red[1][w] + red[2][w];
}

// ---------------- k3: finalize scalar (1 block, 32 warps; warp per 2 bc) ----------------
__global__ __launch_bounds__(1024) void k3(float* __restrict__ out) {
    __shared__ float sM[64][66];
    __shared__ float sla[64], saf[64];
    int tid = threadIdx.x;
    int wi = tid >> 5, lane = tid & 31;

    #pragma unroll
    for (int t = wi * 2; t < wi * 2 + 2; t++) {
        for (int i = lane; i < 66; i += 32) {
            float s = 0.f;
            #pragma unroll
            for (int seg = 0; seg < SEGS; seg++) s += g_MomSeg[(size_t)(t * SEGS + seg) * 66 + i];
            sM[t][i] = s;
        }
        __syncwarp();
        const float* mm = sM[t];
        float V = mm[0];
        float Vf = fmaxf(V, 1.0f);
        float invVf = 1.0f / Vf;

        float Srk = 0.f, nk = 0.f;
        if (lane < 10) {
            Srk = mm[1 + lane];
            int di = 10 * lane - lane * (lane - 1) / 2;
            float cv = mm[11 + di] - Srk * Srk * invVf;
            nk = sqrtf(fmaxf(cv, 0.f));
        }
        float Sr[10], n[10];
        #pragma unroll
        for (int k = 0; k < 10; k++) {
            Sr[k] = __shfl_sync(0xffffffffu, Srk, k);
            n[k]  = __shfl_sync(0xffffffffu, nk, k);
        }
        float acci = 0.f;
        #pragma unroll
        for (int rep = 0; rep < 2; rep++) {
            int p = lane + rep * 32;
            if (p < 45) {
                int k = cPK[p], l = cPL[p];
                int idx = 10 * k - k * (k - 1) / 2 + (l - k);
                float cv = mm[11 + idx] - Sr[k] * Sr[l] * invVf;
                float g = cv / ((n[k] + 1e-8f) * (n[l] + 1e-8f)) * invVf;
                acci += 2.0f * g * g;
            }
        }
        #pragma unroll
        for (int o = 16; o; o >>= 1) acci += __shfl_xor_sync(0xffffffffu, acci, o);
        if (lane == 0) {
            float loss = acci * (1.0f / 90.0f);
            int cc = g_cnt[t];
            float act = (cc >= 1 && V >= 2.0f) ? 1.0f : 0.0f;
            sla[t] = loss * act;
            saf[t] = act;
        }
        __syncwarp();
    }
    __syncthreads();
    if (tid == 0) {
        float s = 0.f;
        #pragma unroll
        for (int b = 0; b < 8; b++) {
            float la = 0.f, af = 0.f;
            #pragma unroll
            for (int c = 0; c < 8; c++) { la += sla[b * 8 + c]; af += saf[b * 8 + c]; }
            s += la / fmaxf(af, 1.0f);
        }
        out[0] = s * 0.125f;
    }
}

// ---------------- launch ----------------
extern "C" void kernel_launch(void* const* d_in, const int* in_sizes, int n_in,
                              void* d_out, int out_size) {
    const float* F  = (const float*)d_in[0];   // feature_map [8,512,96,96]
    const float* P  = (const float*)d_in[1];   // prototypes  [80,512]
    const int*   Mk = (const int*)d_in[2];     // pseudo_mask [8,96,96]
    float* out = (float*)d_out;

    k0_norm_proto<<<81, 128>>>(P);    // #0 (includes g_cnt zeroing)
    k1_sim<<<1024, 288>>>(F, Mk);     // #1
    k1b<<<768, 96>>>(Mk);             // #2
    k2b<<<64 * SEGS, 96>>>();         // #3  <-- profiled this round
    k3<<<1, 1024>>>(out);             // #4
}